// round 14
// baseline (speedup 1.0000x reference)
#include <cuda_runtime.h>
#include <math.h>

#define Nn 50000
#define Ee 1600000
#define Gg 64
#define NB 49   // ceil(Nn/1024)

// ---------------- device scratch ----------------
__device__ float g_h[Nn*64];
__device__ float g_Q[Nn*64];
__device__ float g_S[Nn*64];
__device__ float g_KV[Nn*128];      // per node: pair p (0..31): [K2p,K2p+1,V2p,V2p+1]
__device__ int   g_deg[Nn];
__device__ int   g_rowptr[Nn+1];
__device__ int   g_cursor[Nn];
__device__ int   g_bsum[64];
__device__ int2  g_perm[Ee];
__device__ int   g_srcperm[Ee];
__device__ float g_eaperm[Ee*16];
__device__ float g_pool[Gg*64];
__device__ int   g_cnt[Gg];

// ---------------- f32x2 packed-FMA helpers ----------------
__device__ __forceinline__ unsigned long long pk2(float lo, float hi) {
    unsigned long long r;
    asm("mov.b64 %0,{%1,%2};" : "=l"(r) : "f"(lo), "f"(hi));
    return r;
}
__device__ __forceinline__ void fma2(unsigned long long& d, unsigned long long a, unsigned long long b) {
    asm("fma.rn.f32x2 %0,%1,%2,%0;" : "+l"(d) : "l"(a), "l"(b));
}
__device__ __forceinline__ float2 upk2(unsigned long long v) {
    float2 r;
    asm("mov.b64 {%0,%1},%2;" : "=f"(r.x), "=f"(r.y) : "l"(v));
    return r;
}

// ---------------- zero degree ----------------
__global__ void zero_kernel() {
    int i = blockIdx.x * blockDim.x + threadIdx.x;
    for (; i < Nn; i += gridDim.x * blockDim.x) g_deg[i] = 0;
}

// ---------------- degree histogram ----------------
__global__ void hist_kernel(const int* __restrict__ dst) {
    int e = blockIdx.x * blockDim.x + threadIdx.x;
    if (e < Ee) atomicAdd(&g_deg[dst[e]], 1);
}

// ---------------- scan A ----------------
__global__ void scanA_kernel() {
    __shared__ int sh[1024];
    int tid = threadIdx.x;
    int i = blockIdx.x * 1024 + tid;
    if (blockIdx.x == 0) {
        if (tid < Gg) g_cnt[tid] = 0;
        for (int j = tid; j < Gg*64; j += 1024) g_pool[j] = 0.f;
    }
    int v = (i < Nn) ? g_deg[i] : 0;
    sh[tid] = v;
    __syncthreads();
    for (int off = 1; off < 1024; off <<= 1) {
        int t = (tid >= off) ? sh[tid - off] : 0;
        __syncthreads();
        sh[tid] += t;
        __syncthreads();
    }
    if (i < Nn) g_rowptr[i] = sh[tid] - v;
    if (tid == 1023) g_bsum[blockIdx.x] = sh[1023];
}

// ---------------- scan B+C fused ----------------
__global__ void scanBC_kernel() {
    __shared__ int sh[64];
    __shared__ int carry;
    int t = threadIdx.x;
    if (t < 64) sh[t] = (t < blockIdx.x && t < NB) ? g_bsum[t] : 0;
    __syncthreads();
    if (t == 0) { int s = 0; for (int j = 0; j < 64; j++) s += sh[j]; carry = s; }
    __syncthreads();
    int i = blockIdx.x * 1024 + t;
    if (i < Nn) { int r = g_rowptr[i] + carry; g_rowptr[i] = r; g_cursor[i] = r; }
    if (i == 0) g_rowptr[Nn] = Ee;
}

// ---------------- scatter ----------------
__global__ void scatter_kernel(const int* __restrict__ src,
                               const int* __restrict__ dst) {
    int e = blockIdx.x * blockDim.x + threadIdx.x;
    if (e >= Ee) return;
    int d = dst[e];
    int p = atomicAdd(&g_cursor[d], 1);
    g_perm[p] = make_int2(src[e], e);
}

// ---------------- gather eattr into CSR order ----------------
__global__ void gatherE_kernel(const float* __restrict__ eattr) {
    int t = blockIdx.x * blockDim.x + threadIdx.x;
    if (t >= Ee * 4) return;
    int slot = t >> 2, part = t & 3;
    int2 p = g_perm[slot];
    float4 v = *(const float4*)(eattr + (size_t)p.y * 16 + part * 4);
    *(float4*)(g_eaperm + (size_t)slot * 16 + part * 4) = v;
    if (part == 0) g_srcperm[slot] = p.x;
}

// ---------------- input MLP ----------------
__global__ __launch_bounds__(256, 2) void node_in_kernel(const float* __restrict__ x,
                                                         const float* __restrict__ Wn,
                                                         const float* __restrict__ bn) {
    __shared__ __align__(16) float Ws[32*64];
    __shared__ float bs_[64];
    int t = threadIdx.x;
    for (int i = t; i < 32*64; i += 256) Ws[i] = Wn[i];
    if (t < 64) bs_[t] = bn[t];
    __syncthreads();

    int grp = t >> 3;
    int c8  = (t & 7) * 8;
    int node0 = blockIdx.x * 128 + grp * 4;

    unsigned long long acc[4][4];
    #pragma unroll
    for (int p = 0; p < 4; p++) {
        unsigned long long b = pk2(bs_[c8 + 2*p], bs_[c8 + 2*p + 1]);
        #pragma unroll
        for (int n = 0; n < 4; n++) acc[n][p] = b;
    }

    #pragma unroll 2
    for (int k4 = 0; k4 < 8; k4++) {
        float4 rh[4];
        #pragma unroll
        for (int n = 0; n < 4; n++) {
            int nd = node0 + n; if (nd > Nn - 1) nd = Nn - 1;
            rh[n] = *(const float4*)(x + (size_t)nd*32 + k4*4);
        }
        #pragma unroll
        for (int kk = 0; kk < 4; kk++) {
            int k = k4*4 + kk;
            ulonglong2 w0 = *(const ulonglong2*)&Ws[k*64 + c8];
            ulonglong2 w1 = *(const ulonglong2*)&Ws[k*64 + c8 + 4];
            #pragma unroll
            for (int n = 0; n < 4; n++) {
                float rv = ((const float*)&rh[n])[kk];
                unsigned long long r2 = pk2(rv, rv);
                fma2(acc[n][0], r2, w0.x); fma2(acc[n][1], r2, w0.y);
                fma2(acc[n][2], r2, w1.x); fma2(acc[n][3], r2, w1.y);
            }
        }
    }
    #pragma unroll
    for (int n = 0; n < 4; n++) {
        int nd = node0 + n;
        if (nd < Nn) {
            float2 x0 = upk2(acc[n][0]), x1 = upk2(acc[n][1]);
            float2 x2 = upk2(acc[n][2]), x3 = upk2(acc[n][3]);
            float4 o0 = make_float4(fmaxf(x0.x,0.f), fmaxf(x0.y,0.f), fmaxf(x1.x,0.f), fmaxf(x1.y,0.f));
            float4 o1 = make_float4(fmaxf(x2.x,0.f), fmaxf(x2.y,0.f), fmaxf(x3.x,0.f), fmaxf(x3.y,0.f));
            *(float4*)(g_h + (size_t)nd*64 + c8)     = o0;
            *(float4*)(g_h + (size_t)nd*64 + c8 + 4) = o1;
        }
    }
}

// ---------------- merged dual-GEMM: blocks [0,nblk): (Q,K), [nblk,2nblk): (V,S) ----------------
__global__ __launch_bounds__(256, 2) void gemm2_kernel(const float* __restrict__ Wq, const float* __restrict__ bq,
                                                       const float* __restrict__ Wk, const float* __restrict__ bk,
                                                       const float* __restrict__ Wv, const float* __restrict__ bv,
                                                       const float* __restrict__ Wsk, const float* __restrict__ bsk,
                                                       int nblk) {
    __shared__ __align__(16) float WAs[4096];
    __shared__ __align__(16) float WBs[4096];
    __shared__ float bAs[64], bBs[64];
    int sel = blockIdx.x >= nblk;
    int blk = sel ? blockIdx.x - nblk : blockIdx.x;
    const float* WA = sel ? Wv : Wq;  const float* bA = sel ? bv : bq;
    const float* WB = sel ? Wsk : Wk; const float* bB = sel ? bsk : bk;
    int t = threadIdx.x;
    for (int i = t; i < 4096; i += 256) { WAs[i] = WA[i]; WBs[i] = WB[i]; }
    if (t < 64) { bAs[t] = bA[t]; bBs[t] = bB[t]; }
    __syncthreads();

    int grp = t >> 3;
    int c8  = (t & 7) * 8;
    int node0 = blk * 128 + grp * 4;

    unsigned long long accA[4][4], accB[4][4];
    #pragma unroll
    for (int p = 0; p < 4; p++) {
        unsigned long long ba = pk2(bAs[c8 + 2*p], bAs[c8 + 2*p + 1]);
        unsigned long long bb = pk2(bBs[c8 + 2*p], bBs[c8 + 2*p + 1]);
        #pragma unroll
        for (int n = 0; n < 4; n++) { accA[n][p] = ba; accB[n][p] = bb; }
    }

    #pragma unroll 2
    for (int k4 = 0; k4 < 16; k4++) {
        float4 rh[4];
        #pragma unroll
        for (int n = 0; n < 4; n++) {
            int nd = node0 + n; if (nd > Nn - 1) nd = Nn - 1;
            rh[n] = *(const float4*)(g_h + (size_t)nd*64 + k4*4);
        }
        #pragma unroll
        for (int kk = 0; kk < 4; kk++) {
            int k = k4*4 + kk;
            ulonglong2 wa0 = *(const ulonglong2*)&WAs[k*64 + c8];
            ulonglong2 wa1 = *(const ulonglong2*)&WAs[k*64 + c8 + 4];
            ulonglong2 wb0 = *(const ulonglong2*)&WBs[k*64 + c8];
            ulonglong2 wb1 = *(const ulonglong2*)&WBs[k*64 + c8 + 4];
            #pragma unroll
            for (int n = 0; n < 4; n++) {
                float rv = ((const float*)&rh[n])[kk];
                unsigned long long r2 = pk2(rv, rv);
                fma2(accA[n][0], r2, wa0.x); fma2(accA[n][1], r2, wa0.y);
                fma2(accA[n][2], r2, wa1.x); fma2(accA[n][3], r2, wa1.y);
                fma2(accB[n][0], r2, wb0.x); fma2(accB[n][1], r2, wb0.y);
                fma2(accB[n][2], r2, wb1.x); fma2(accB[n][3], r2, wb1.y);
            }
        }
    }

    #pragma unroll
    for (int n = 0; n < 4; n++) {
        int nd = node0 + n;
        if (nd >= Nn) continue;
        if (!sel) {
            // A -> Q (contiguous), B -> K slots of KV
            float2 a0 = upk2(accA[n][0]), a1 = upk2(accA[n][1]);
            float2 a2 = upk2(accA[n][2]), a3 = upk2(accA[n][3]);
            *(float4*)(g_Q + (size_t)nd*64 + c8)     = make_float4(a0.x, a0.y, a1.x, a1.y);
            *(float4*)(g_Q + (size_t)nd*64 + c8 + 4) = make_float4(a2.x, a2.y, a3.x, a3.y);
            #pragma unroll
            for (int p = 0; p < 4; p++)
                *(unsigned long long*)(g_KV + (size_t)nd*128 + c8*2 + p*4) = accB[n][p];
        } else {
            // A -> V slots of KV, B -> S (contiguous)
            #pragma unroll
            for (int p = 0; p < 4; p++)
                *(unsigned long long*)(g_KV + (size_t)nd*128 + c8*2 + p*4 + 2) = accA[n][p];
            float2 b0 = upk2(accB[n][0]), b1 = upk2(accB[n][1]);
            float2 b2 = upk2(accB[n][2]), b3 = upk2(accB[n][3]);
            *(float4*)(g_S + (size_t)nd*64 + c8)     = make_float4(b0.x, b0.y, b1.x, b1.y);
            *(float4*)(g_S + (size_t)nd*64 + c8 + 4) = make_float4(b2.x, b2.y, b3.x, b3.y);
        }
    }
}

// ---------------- attention ----------------
struct AState { float m, d, avx, avy, awx, awy; };

__device__ __forceinline__ void step4(AState& st, int i, int lane, int d2,
                                      float2 q, float2 u) {
    int s0 = g_srcperm[i], s1 = g_srcperm[i+1], s2 = g_srcperm[i+2], s3 = g_srcperm[i+3];
    float4 KV0 = *(const float4*)(g_KV + (size_t)s0*128 + lane*4);
    float4 KV1 = *(const float4*)(g_KV + (size_t)s1*128 + lane*4);
    float4 KV2 = *(const float4*)(g_KV + (size_t)s2*128 + lane*4);
    float4 KV3 = *(const float4*)(g_KV + (size_t)s3*128 + lane*4);
    float2 E0 = *(const float2*)(g_eaperm + (size_t)(i+0)*16 + d2);
    float2 E1 = *(const float2*)(g_eaperm + (size_t)(i+1)*16 + d2);
    float2 E2 = *(const float2*)(g_eaperm + (size_t)(i+2)*16 + d2);
    float2 E3 = *(const float2*)(g_eaperm + (size_t)(i+3)*16 + d2);

    float t0 = q.x*KV0.x + q.y*KV0.y + u.x*E0.x + u.y*E0.y;
    float t1 = q.x*KV1.x + q.y*KV1.y + u.x*E1.x + u.y*E1.y;
    float t2 = q.x*KV2.x + q.y*KV2.y + u.x*E2.x + u.y*E2.y;
    float t3 = q.x*KV3.x + q.y*KV3.y + u.x*E3.x + u.y*E3.y;
    t0 += __shfl_xor_sync(0xffffffffu, t0, 1);
    t1 += __shfl_xor_sync(0xffffffffu, t1, 1);
    t2 += __shfl_xor_sync(0xffffffffu, t2, 1);
    t3 += __shfl_xor_sync(0xffffffffu, t3, 1);
    t0 += __shfl_xor_sync(0xffffffffu, t0, 2);
    t1 += __shfl_xor_sync(0xffffffffu, t1, 2);
    t2 += __shfl_xor_sync(0xffffffffu, t2, 2);
    t3 += __shfl_xor_sync(0xffffffffu, t3, 2);
    t0 += __shfl_xor_sync(0xffffffffu, t0, 4);
    t1 += __shfl_xor_sync(0xffffffffu, t1, 4);
    t2 += __shfl_xor_sync(0xffffffffu, t2, 4);
    t3 += __shfl_xor_sync(0xffffffffu, t3, 4);
    float a0 = t0*0.25f, a1 = t1*0.25f, a2 = t2*0.25f, a3 = t3*0.25f;

    float mn = fmaxf(fmaxf(fmaxf(a0, a1), fmaxf(a2, a3)), st.m);
    float corr = __expf(st.m - mn);
    float w0 = __expf(a0 - mn), w1 = __expf(a1 - mn);
    float w2 = __expf(a2 - mn), w3 = __expf(a3 - mn);
    st.d   = st.d*corr   + (w0 + w1) + (w2 + w3);
    st.avx = st.avx*corr + (w0*KV0.z + w1*KV1.z) + (w2*KV2.z + w3*KV3.z);
    st.avy = st.avy*corr + (w0*KV0.w + w1*KV1.w) + (w2*KV2.w + w3*KV3.w);
    st.awx = st.awx*corr + (w0*E0.x + w1*E1.x) + (w2*E2.x + w3*E3.x);
    st.awy = st.awy*corr + (w0*E0.y + w1*E1.y) + (w2*E2.y + w3*E3.y);
    st.m = mn;
}

__device__ __forceinline__ void step1(AState& st, int i, int lane, int d2,
                                      float2 q, float2 u) {
    int s0 = g_srcperm[i];
    float4 KV0 = *(const float4*)(g_KV + (size_t)s0*128 + lane*4);
    float2 E0 = *(const float2*)(g_eaperm + (size_t)i*16 + d2);
    float t0 = q.x*KV0.x + q.y*KV0.y + u.x*E0.x + u.y*E0.y;
    t0 += __shfl_xor_sync(0xffffffffu, t0, 1);
    t0 += __shfl_xor_sync(0xffffffffu, t0, 2);
    t0 += __shfl_xor_sync(0xffffffffu, t0, 4);
    float a0 = t0*0.25f;
    float mn = fmaxf(st.m, a0);
    float corr = __expf(st.m - mn);
    float w0 = __expf(a0 - mn);
    st.d   = st.d*corr   + w0;
    st.avx = st.avx*corr + w0*KV0.z;
    st.avy = st.avy*corr + w0*KV0.w;
    st.awx = st.awx*corr + w0*E0.x;
    st.awy = st.awy*corr + w0*E0.y;
    st.m = mn;
}

__global__ __launch_bounds__(256) void attn_kernel(const float* __restrict__ Wel) {
    __shared__ float WEs[1024];    // We[j*64 + c]
    __shared__ float WEsT[1024];   // WEsT[ch*16 + j] = We[j][ch]
    for (int i = threadIdx.x; i < 1024; i += 256) {
        WEs[i] = Wel[i];
        int ch = i >> 4, j = i & 15;
        WEsT[i] = Wel[j*64 + ch];
    }
    __syncthreads();

    int wid  = (blockIdx.x * blockDim.x + threadIdx.x) >> 5;
    int lane = threadIdx.x & 31;
    if (wid >= Nn) return;

    int hh = lane >> 3;
    int d2 = (lane & 7) * 2;

    float2 q = *(const float2*)(g_Q + (size_t)wid*64 + 2*lane);

    // u = We^T q for this head (once per node)
    float ux = 0.f, uy = 0.f;
    #pragma unroll
    for (int cc = 0; cc < 16; cc++) {
        float qv = __shfl_sync(0xffffffffu, (cc & 1) ? q.y : q.x, (hh << 3) + (cc >> 1));
        ux = fmaf(qv, WEsT[((hh << 4) + cc)*16 + d2],     ux);
        uy = fmaf(qv, WEsT[((hh << 4) + cc)*16 + d2 + 1], uy);
    }
    float2 u = make_float2(ux, uy);

    int beg = g_rowptr[wid], end = g_rowptr[wid + 1];
    AState A = { -INFINITY, 0.f, 0.f, 0.f, 0.f, 0.f };
    AState B = { -INFINITY, 0.f, 0.f, 0.f, 0.f, 0.f };

    int i = beg;
    for (; i + 8 <= end; i += 8) {
        step4(A, i,     lane, d2, q, u);
        step4(B, i + 4, lane, d2, q, u);
    }
    for (; i + 4 <= end; i += 4) step4(A, i, lane, d2, q, u);
    for (; i < end; i++)         step1(A, i, lane, d2, q, u);

    // merge the two online-softmax states
    float M  = fmaxf(A.m, B.m);
    float cA = (A.d > 0.f) ? __expf(A.m - M) : 0.f;
    float cB = (B.d > 0.f) ? __expf(B.m - M) : 0.f;
    float dsum = A.d*cA + B.d*cB;
    float avx = A.avx*cA + B.avx*cB;
    float avy = A.avy*cA + B.avy*cB;
    float awx = A.awx*cA + B.awx*cB;
    float awy = A.awy*cA + B.awy*cB;

    float ox = avx, oy = avy;
    #pragma unroll
    for (int jj = 0; jj < 8; jj++) {
        int srcl = (hh << 3) + jj;
        float bx = __shfl_sync(0xffffffffu, awx, srcl);
        float by = __shfl_sync(0xffffffffu, awy, srcl);
        ox = fmaf(bx, WEs[(2*jj)*64 + 2*lane],       ox);
        oy = fmaf(bx, WEs[(2*jj)*64 + 2*lane + 1],   oy);
        ox = fmaf(by, WEs[(2*jj+1)*64 + 2*lane],     ox);
        oy = fmaf(by, WEs[(2*jj+1)*64 + 2*lane + 1], oy);
    }
    float inv = 1.f / (dsum + 1e-16f);
    float2 sv = *(const float2*)(g_S + (size_t)wid*64 + 2*lane);
    float o0 = fmaxf(fmaf(ox, inv, sv.x), 0.f);
    float o1 = fmaxf(fmaf(oy, inv, sv.y), 0.f);
    float2* hp = (float2*)(g_h + (size_t)wid*64 + 2*lane);
    float2 hv = *hp;
    hv.x += o0; hv.y += o1;
    *hp = hv;
}

// ---------------- pool ----------------
__global__ void pool_kernel(const int* __restrict__ batch) {
    int c = threadIdx.x & 63;
    int sub = threadIdx.x >> 6;
    int start = blockIdx.x * 1024 + sub * 256;
    if (start >= Nn) return;
    int end = min(start + 256, Nn);
    int gprev = batch[start];
    float acc = 0.f;
    int cnt = 0;
    for (int node = start; node < end; node++) {
        int g = batch[node];
        float v = g_h[(size_t)node*64 + c];
        if (g != gprev) {
            atomicAdd(&g_pool[gprev*64 + c], acc);
            if (c == 0) atomicAdd(&g_cnt[gprev], cnt);
            acc = 0.f; cnt = 0; gprev = g;
        }
        acc += v; cnt++;
    }
    atomicAdd(&g_pool[gprev*64 + c], acc);
    if (c == 0) atomicAdd(&g_cnt[gprev], cnt);
}

// ---------------- head MLP ----------------
__global__ void final_kernel(const float* __restrict__ W1, const float* __restrict__ b1,
                             const float* __restrict__ W2, const float* __restrict__ b2,
                             float* __restrict__ out) {
    int g = blockIdx.x;
    int j = threadIdx.x;
    float invc = 1.f / fmaxf((float)g_cnt[g], 1.f);
    float acc = b1[j];
    #pragma unroll
    for (int k = 0; k < 64; k++)
        acc = fmaf(g_pool[g*64 + k] * invc, W1[k*32 + j], acc);
    acc = fmaxf(acc, 0.f);
    float t = acc * W2[j];
    #pragma unroll
    for (int o = 16; o > 0; o >>= 1) t += __shfl_xor_sync(0xffffffffu, t, o);
    if (j == 0) out[g] = t + b2[0];
}

// ---------------- launch ----------------
extern "C" void kernel_launch(void* const* d_in, const int* in_sizes, int n_in,
                              void* d_out, int out_size) {
    const float* x     = (const float*)d_in[0];
    const int*   ei    = (const int*)  d_in[1];
    const float* eattr = (const float*)d_in[2];
    const int*   batch = (const int*)  d_in[3];
    const float* Wn = (const float*)d_in[4];  const float* bn = (const float*)d_in[5];
    const float* Wq = (const float*)d_in[6];  const float* bq = (const float*)d_in[7];
    const float* Wk = (const float*)d_in[8];  const float* bk = (const float*)d_in[9];
    const float* Wv = (const float*)d_in[10]; const float* bv = (const float*)d_in[11];
    const float* We = (const float*)d_in[12];
    const float* Ws = (const float*)d_in[13]; const float* bs = (const float*)d_in[14];
    const float* W1 = (const float*)d_in[15]; const float* b1 = (const float*)d_in[16];
    const float* W2 = (const float*)d_in[17]; const float* b2 = (const float*)d_in[18];
    float* out = (float*)d_out;

    const int* src = ei;
    const int* dst = ei + Ee;

    int nblk = (Nn + 127) / 128;   // 391
    // order: capture slot #3 lands on merged gemm2 (layer 0)
    node_in_kernel<<<nblk, 256>>>(x, Wn, bn);                         // 0
    zero_kernel<<<64, 256>>>();                                       // 1
    hist_kernel<<<(Ee + 255)/256, 256>>>(dst);                        // 2
    gemm2_kernel<<<2*nblk, 256>>>(Wq, bq, Wk, bk, Wv, bv, Ws, bs, nblk); // 3
    scanA_kernel<<<NB, 1024>>>();                                     // 4
    scanBC_kernel<<<NB, 1024>>>();                                    // 5
    scatter_kernel<<<(Ee + 255)/256, 256>>>(src, dst);                // 6
    gatherE_kernel<<<(Ee*4 + 255)/256, 256>>>(eattr);                 // 7
    attn_kernel<<<(Nn*32 + 255)/256, 256>>>(We);                      // 8

    for (int l = 1; l < 3; l++) {
        const float* Wql = Wq + (size_t)l*64*64; const float* bql = bq + (size_t)l*64;
        const float* Wkl = Wk + (size_t)l*64*64; const float* bkl = bk + (size_t)l*64;
        const float* Wvl = Wv + (size_t)l*64*64; const float* bvl = bv + (size_t)l*64;
        const float* Wsl = Ws + (size_t)l*64*64; const float* bsl = bs + (size_t)l*64;
        const float* Wel = We + (size_t)l*16*64;
        gemm2_kernel<<<2*nblk, 256>>>(Wql, bql, Wkl, bkl, Wvl, bvl, Wsl, bsl, nblk);
        attn_kernel<<<(Nn*32 + 255)/256, 256>>>(Wel);
    }

    pool_kernel<<<(Nn + 1023)/1024, 256>>>(batch);
    final_kernel<<<Gg, 32>>>(W1, b1, W2, b2, out);
}

// round 15
// speedup vs baseline: 1.1078x; 1.1078x over previous
#include <cuda_runtime.h>
#include <cuda_fp16.h>
#include <math.h>

#define Nn 50000
#define Ee 1600000
#define Gg 64
#define NB 49   // ceil(Nn/1024)

// ---------------- device scratch ----------------
__device__ float g_h[Nn*64];
__device__ float g_Q[Nn*64];
__device__ float g_S[Nn*64];
__device__ uint2 g_KVh[Nn*32];      // [node][lane] = {half2 K(2l,2l+1), half2 V(2l,2l+1)}
__device__ int   g_deg[Nn];
__device__ int   g_rowptr[Nn+1];
__device__ int   g_cursor[Nn];
__device__ int   g_bsum[64];
__device__ int2  g_perm[Ee];
__device__ int   g_srcperm[Ee];
__device__ __half2 g_eah[Ee*8];     // eattr permuted, fp16: 8 half2 per edge
__device__ float g_pool[Gg*64];
__device__ int   g_cnt[Gg];

// ---------------- f32x2 packed-FMA helpers ----------------
__device__ __forceinline__ unsigned long long pk2(float lo, float hi) {
    unsigned long long r;
    asm("mov.b64 %0,{%1,%2};" : "=l"(r) : "f"(lo), "f"(hi));
    return r;
}
__device__ __forceinline__ void fma2(unsigned long long& d, unsigned long long a, unsigned long long b) {
    asm("fma.rn.f32x2 %0,%1,%2,%0;" : "+l"(d) : "l"(a), "l"(b));
}
__device__ __forceinline__ float2 upk2(unsigned long long v) {
    float2 r;
    asm("mov.b64 {%0,%1},%2;" : "=f"(r.x), "=f"(r.y) : "l"(v));
    return r;
}

// ---------------- zero degree ----------------
__global__ void zero_kernel() {
    int i = blockIdx.x * blockDim.x + threadIdx.x;
    for (; i < Nn; i += gridDim.x * blockDim.x) g_deg[i] = 0;
}

// ---------------- degree histogram ----------------
__global__ void hist_kernel(const int* __restrict__ dst) {
    int e = blockIdx.x * blockDim.x + threadIdx.x;
    if (e < Ee) atomicAdd(&g_deg[dst[e]], 1);
}

// ---------------- scan A ----------------
__global__ void scanA_kernel() {
    __shared__ int sh[1024];
    int tid = threadIdx.x;
    int i = blockIdx.x * 1024 + tid;
    if (blockIdx.x == 0) {
        if (tid < Gg) g_cnt[tid] = 0;
        for (int j = tid; j < Gg*64; j += 1024) g_pool[j] = 0.f;
    }
    int v = (i < Nn) ? g_deg[i] : 0;
    sh[tid] = v;
    __syncthreads();
    for (int off = 1; off < 1024; off <<= 1) {
        int t = (tid >= off) ? sh[tid - off] : 0;
        __syncthreads();
        sh[tid] += t;
        __syncthreads();
    }
    if (i < Nn) g_rowptr[i] = sh[tid] - v;
    if (tid == 1023) g_bsum[blockIdx.x] = sh[1023];
}

// ---------------- scan B+C fused ----------------
__global__ void scanBC_kernel() {
    __shared__ int sh[64];
    __shared__ int carry;
    int t = threadIdx.x;
    if (t < 64) sh[t] = (t < blockIdx.x && t < NB) ? g_bsum[t] : 0;
    __syncthreads();
    if (t == 0) { int s = 0; for (int j = 0; j < 64; j++) s += sh[j]; carry = s; }
    __syncthreads();
    int i = blockIdx.x * 1024 + t;
    if (i < Nn) { int r = g_rowptr[i] + carry; g_rowptr[i] = r; g_cursor[i] = r; }
    if (i == 0) g_rowptr[Nn] = Ee;
}

// ---------------- scatter ----------------
__global__ void scatter_kernel(const int* __restrict__ src,
                               const int* __restrict__ dst) {
    int e = blockIdx.x * blockDim.x + threadIdx.x;
    if (e >= Ee) return;
    int d = dst[e];
    int p = atomicAdd(&g_cursor[d], 1);
    g_perm[p] = make_int2(src[e], e);
}

// ---------------- gather eattr into CSR order, convert to fp16 ----------------
__global__ void gatherE_kernel(const float* __restrict__ eattr) {
    int t = blockIdx.x * blockDim.x + threadIdx.x;
    if (t >= Ee * 2) return;
    int slot = t >> 1, part = t & 1;
    int2 p = g_perm[slot];
    const float4* s = (const float4*)(eattr + (size_t)p.y * 16 + part * 8);
    float4 a = s[0], b = s[1];
    __half2 h0 = __floats2half2_rn(a.x, a.y);
    __half2 h1 = __floats2half2_rn(a.z, a.w);
    __half2 h2 = __floats2half2_rn(b.x, b.y);
    __half2 h3 = __floats2half2_rn(b.z, b.w);
    uint2* o = (uint2*)(g_eah + (size_t)slot * 8 + part * 4);
    o[0] = make_uint2(*(unsigned*)&h0, *(unsigned*)&h1);
    o[1] = make_uint2(*(unsigned*)&h2, *(unsigned*)&h3);
    if (part == 0) g_srcperm[slot] = p.x;
}

// ---------------- input MLP ----------------
__global__ __launch_bounds__(256, 2) void node_in_kernel(const float* __restrict__ x,
                                                         const float* __restrict__ Wn,
                                                         const float* __restrict__ bn) {
    __shared__ __align__(16) float Ws[32*64];
    __shared__ float bs_[64];
    int t = threadIdx.x;
    for (int i = t; i < 32*64; i += 256) Ws[i] = Wn[i];
    if (t < 64) bs_[t] = bn[t];
    __syncthreads();

    int grp = t >> 3;
    int c8  = (t & 7) * 8;
    int node0 = blockIdx.x * 128 + grp * 4;

    unsigned long long acc[4][4];
    #pragma unroll
    for (int p = 0; p < 4; p++) {
        unsigned long long b = pk2(bs_[c8 + 2*p], bs_[c8 + 2*p + 1]);
        #pragma unroll
        for (int n = 0; n < 4; n++) acc[n][p] = b;
    }

    #pragma unroll 2
    for (int k4 = 0; k4 < 8; k4++) {
        float4 rh[4];
        #pragma unroll
        for (int n = 0; n < 4; n++) {
            int nd = node0 + n; if (nd > Nn - 1) nd = Nn - 1;
            rh[n] = *(const float4*)(x + (size_t)nd*32 + k4*4);
        }
        #pragma unroll
        for (int kk = 0; kk < 4; kk++) {
            int k = k4*4 + kk;
            ulonglong2 w0 = *(const ulonglong2*)&Ws[k*64 + c8];
            ulonglong2 w1 = *(const ulonglong2*)&Ws[k*64 + c8 + 4];
            #pragma unroll
            for (int n = 0; n < 4; n++) {
                float rv = ((const float*)&rh[n])[kk];
                unsigned long long r2 = pk2(rv, rv);
                fma2(acc[n][0], r2, w0.x); fma2(acc[n][1], r2, w0.y);
                fma2(acc[n][2], r2, w1.x); fma2(acc[n][3], r2, w1.y);
            }
        }
    }
    #pragma unroll
    for (int n = 0; n < 4; n++) {
        int nd = node0 + n;
        if (nd < Nn) {
            float2 x0 = upk2(acc[n][0]), x1 = upk2(acc[n][1]);
            float2 x2 = upk2(acc[n][2]), x3 = upk2(acc[n][3]);
            float4 o0 = make_float4(fmaxf(x0.x,0.f), fmaxf(x0.y,0.f), fmaxf(x1.x,0.f), fmaxf(x1.y,0.f));
            float4 o1 = make_float4(fmaxf(x2.x,0.f), fmaxf(x2.y,0.f), fmaxf(x3.x,0.f), fmaxf(x3.y,0.f));
            *(float4*)(g_h + (size_t)nd*64 + c8)     = o0;
            *(float4*)(g_h + (size_t)nd*64 + c8 + 4) = o1;
        }
    }
}

// ---------------- merged dual-GEMM: blocks [0,nblk): (Q,K), [nblk,2nblk): (V,S) ----------------
__global__ __launch_bounds__(256, 2) void gemm2_kernel(const float* __restrict__ Wq, const float* __restrict__ bq,
                                                       const float* __restrict__ Wk, const float* __restrict__ bk,
                                                       const float* __restrict__ Wv, const float* __restrict__ bv,
                                                       const float* __restrict__ Wsk, const float* __restrict__ bsk,
                                                       int nblk) {
    __shared__ __align__(16) float WAs[4096];
    __shared__ __align__(16) float WBs[4096];
    __shared__ float bAs[64], bBs[64];
    int sel = blockIdx.x >= nblk;
    int blk = sel ? blockIdx.x - nblk : blockIdx.x;
    const float* WA = sel ? Wv : Wq;  const float* bA = sel ? bv : bq;
    const float* WB = sel ? Wsk : Wk; const float* bB = sel ? bsk : bk;
    int t = threadIdx.x;
    for (int i = t; i < 4096; i += 256) { WAs[i] = WA[i]; WBs[i] = WB[i]; }
    if (t < 64) { bAs[t] = bA[t]; bBs[t] = bB[t]; }
    __syncthreads();

    int grp = t >> 3;
    int c8  = (t & 7) * 8;
    int node0 = blk * 128 + grp * 4;

    unsigned long long accA[4][4], accB[4][4];
    #pragma unroll
    for (int p = 0; p < 4; p++) {
        unsigned long long ba = pk2(bAs[c8 + 2*p], bAs[c8 + 2*p + 1]);
        unsigned long long bb = pk2(bBs[c8 + 2*p], bBs[c8 + 2*p + 1]);
        #pragma unroll
        for (int n = 0; n < 4; n++) { accA[n][p] = ba; accB[n][p] = bb; }
    }

    #pragma unroll 2
    for (int k4 = 0; k4 < 16; k4++) {
        float4 rh[4];
        #pragma unroll
        for (int n = 0; n < 4; n++) {
            int nd = node0 + n; if (nd > Nn - 1) nd = Nn - 1;
            rh[n] = *(const float4*)(g_h + (size_t)nd*64 + k4*4);
        }
        #pragma unroll
        for (int kk = 0; kk < 4; kk++) {
            int k = k4*4 + kk;
            ulonglong2 wa0 = *(const ulonglong2*)&WAs[k*64 + c8];
            ulonglong2 wa1 = *(const ulonglong2*)&WAs[k*64 + c8 + 4];
            ulonglong2 wb0 = *(const ulonglong2*)&WBs[k*64 + c8];
            ulonglong2 wb1 = *(const ulonglong2*)&WBs[k*64 + c8 + 4];
            #pragma unroll
            for (int n = 0; n < 4; n++) {
                float rv = ((const float*)&rh[n])[kk];
                unsigned long long r2 = pk2(rv, rv);
                fma2(accA[n][0], r2, wa0.x); fma2(accA[n][1], r2, wa0.y);
                fma2(accA[n][2], r2, wa1.x); fma2(accA[n][3], r2, wa1.y);
                fma2(accB[n][0], r2, wb0.x); fma2(accB[n][1], r2, wb0.y);
                fma2(accB[n][2], r2, wb1.x); fma2(accB[n][3], r2, wb1.y);
            }
        }
    }

    #pragma unroll
    for (int n = 0; n < 4; n++) {
        int nd = node0 + n;
        if (nd >= Nn) continue;
        unsigned* KVu = (unsigned*)(g_KVh + (size_t)nd*32);
        if (!sel) {
            // A -> Q (fp32), B -> K halves of KVh (.x slots)
            float2 a0 = upk2(accA[n][0]), a1 = upk2(accA[n][1]);
            float2 a2 = upk2(accA[n][2]), a3 = upk2(accA[n][3]);
            *(float4*)(g_Q + (size_t)nd*64 + c8)     = make_float4(a0.x, a0.y, a1.x, a1.y);
            *(float4*)(g_Q + (size_t)nd*64 + c8 + 4) = make_float4(a2.x, a2.y, a3.x, a3.y);
            #pragma unroll
            for (int p = 0; p < 4; p++) {
                float2 kv = upk2(accB[n][p]);
                __half2 h = __floats2half2_rn(kv.x, kv.y);
                KVu[(c8/2 + p)*2 + 0] = *(unsigned*)&h;
            }
        } else {
            // A -> V halves of KVh (.y slots), B -> S (fp32)
            #pragma unroll
            for (int p = 0; p < 4; p++) {
                float2 vv = upk2(accA[n][p]);
                __half2 h = __floats2half2_rn(vv.x, vv.y);
                KVu[(c8/2 + p)*2 + 1] = *(unsigned*)&h;
            }
            float2 b0 = upk2(accB[n][0]), b1 = upk2(accB[n][1]);
            float2 b2 = upk2(accB[n][2]), b3 = upk2(accB[n][3]);
            *(float4*)(g_S + (size_t)nd*64 + c8)     = make_float4(b0.x, b0.y, b1.x, b1.y);
            *(float4*)(g_S + (size_t)nd*64 + c8 + 4) = make_float4(b2.x, b2.y, b3.x, b3.y);
        }
    }
}

// ---------------- attention: warp per dst, online softmax, fp16 KV/E gathers ----------------
__global__ __launch_bounds__(256) void attn_kernel(const float* __restrict__ Wel) {
    __shared__ float WEs[1024];    // We[j*64 + c]
    __shared__ float WEsT[1024];   // WEsT[ch*16 + j] = We[j][ch]
    for (int i = threadIdx.x; i < 1024; i += 256) {
        WEs[i] = Wel[i];
        int ch = i >> 4, j = i & 15;
        WEsT[i] = Wel[j*64 + ch];
    }
    __syncthreads();

    int wid  = (blockIdx.x * blockDim.x + threadIdx.x) >> 5;
    int lane = threadIdx.x & 31;
    if (wid >= Nn) return;

    int hh = lane >> 3;
    int e8 = lane & 7;             // which half2 of the edge's 8

    float2 q = *(const float2*)(g_Q + (size_t)wid*64 + 2*lane);

    // u = We^T q for this head (once per node)
    float ux = 0.f, uy = 0.f;
    #pragma unroll
    for (int cc = 0; cc < 16; cc++) {
        float qv = __shfl_sync(0xffffffffu, (cc & 1) ? q.y : q.x, (hh << 3) + (cc >> 1));
        ux = fmaf(qv, WEsT[((hh << 4) + cc)*16 + 2*e8],     ux);
        uy = fmaf(qv, WEsT[((hh << 4) + cc)*16 + 2*e8 + 1], uy);
    }
    float2 u = make_float2(ux, uy);

    int beg = g_rowptr[wid], end = g_rowptr[wid + 1];
    float m = -INFINITY, dsum = 0.f;
    float avx = 0.f, avy = 0.f, awx = 0.f, awy = 0.f;

    int i = beg;
    for (; i + 4 <= end; i += 4) {
        int s0 = g_srcperm[i], s1 = g_srcperm[i+1], s2 = g_srcperm[i+2], s3 = g_srcperm[i+3];
        uint2 kv0 = g_KVh[(size_t)s0*32 + lane];
        uint2 kv1 = g_KVh[(size_t)s1*32 + lane];
        uint2 kv2 = g_KVh[(size_t)s2*32 + lane];
        uint2 kv3 = g_KVh[(size_t)s3*32 + lane];
        __half2 eh0 = g_eah[(size_t)(i+0)*8 + e8];
        __half2 eh1 = g_eah[(size_t)(i+1)*8 + e8];
        __half2 eh2 = g_eah[(size_t)(i+2)*8 + e8];
        __half2 eh3 = g_eah[(size_t)(i+3)*8 + e8];
        float2 K0 = __half22float2(*(__half2*)&kv0.x), V0 = __half22float2(*(__half2*)&kv0.y);
        float2 K1 = __half22float2(*(__half2*)&kv1.x), V1 = __half22float2(*(__half2*)&kv1.y);
        float2 K2 = __half22float2(*(__half2*)&kv2.x), V2 = __half22float2(*(__half2*)&kv2.y);
        float2 K3 = __half22float2(*(__half2*)&kv3.x), V3 = __half22float2(*(__half2*)&kv3.y);
        float2 E0 = __half22float2(eh0), E1 = __half22float2(eh1);
        float2 E2 = __half22float2(eh2), E3 = __half22float2(eh3);

        float t0 = q.x*K0.x + q.y*K0.y + u.x*E0.x + u.y*E0.y;
        float t1 = q.x*K1.x + q.y*K1.y + u.x*E1.x + u.y*E1.y;
        float t2 = q.x*K2.x + q.y*K2.y + u.x*E2.x + u.y*E2.y;
        float t3 = q.x*K3.x + q.y*K3.y + u.x*E3.x + u.y*E3.y;
        t0 += __shfl_xor_sync(0xffffffffu, t0, 1);
        t1 += __shfl_xor_sync(0xffffffffu, t1, 1);
        t2 += __shfl_xor_sync(0xffffffffu, t2, 1);
        t3 += __shfl_xor_sync(0xffffffffu, t3, 1);
        t0 += __shfl_xor_sync(0xffffffffu, t0, 2);
        t1 += __shfl_xor_sync(0xffffffffu, t1, 2);
        t2 += __shfl_xor_sync(0xffffffffu, t2, 2);
        t3 += __shfl_xor_sync(0xffffffffu, t3, 2);
        t0 += __shfl_xor_sync(0xffffffffu, t0, 4);
        t1 += __shfl_xor_sync(0xffffffffu, t1, 4);
        t2 += __shfl_xor_sync(0xffffffffu, t2, 4);
        t3 += __shfl_xor_sync(0xffffffffu, t3, 4);
        float a0 = t0*0.25f, a1 = t1*0.25f, a2 = t2*0.25f, a3 = t3*0.25f;

        float mn = fmaxf(fmaxf(fmaxf(a0, a1), fmaxf(a2, a3)), m);
        float corr = __expf(m - mn);
        float w0 = __expf(a0 - mn), w1 = __expf(a1 - mn);
        float w2 = __expf(a2 - mn), w3 = __expf(a3 - mn);
        dsum = dsum*corr + (w0 + w1) + (w2 + w3);
        avx = avx*corr + (w0*V0.x + w1*V1.x) + (w2*V2.x + w3*V3.x);
        avy = avy*corr + (w0*V0.y + w1*V1.y) + (w2*V2.y + w3*V3.y);
        awx = awx*corr + (w0*E0.x + w1*E1.x) + (w2*E2.x + w3*E3.x);
        awy = awy*corr + (w0*E0.y + w1*E1.y) + (w2*E2.y + w3*E3.y);
        m = mn;
    }
    for (; i < end; i++) {
        int s0 = g_srcperm[i];
        uint2 kv0 = g_KVh[(size_t)s0*32 + lane];
        __half2 eh0 = g_eah[(size_t)i*8 + e8];
        float2 K0 = __half22float2(*(__half2*)&kv0.x), V0 = __half22float2(*(__half2*)&kv0.y);
        float2 E0 = __half22float2(eh0);
        float t0 = q.x*K0.x + q.y*K0.y + u.x*E0.x + u.y*E0.y;
        t0 += __shfl_xor_sync(0xffffffffu, t0, 1);
        t0 += __shfl_xor_sync(0xffffffffu, t0, 2);
        t0 += __shfl_xor_sync(0xffffffffu, t0, 4);
        float a0 = t0*0.25f;
        float mn = fmaxf(m, a0);
        float corr = __expf(m - mn);
        float w0 = __expf(a0 - mn);
        dsum = dsum*corr + w0;
        avx = avx*corr + w0*V0.x;
        avy = avy*corr + w0*V0.y;
        awx = awx*corr + w0*E0.x;
        awy = awy*corr + w0*E0.y;
        m = mn;
    }

    float ox = avx, oy = avy;
    #pragma unroll
    for (int jj = 0; jj < 8; jj++) {
        int srcl = (hh << 3) + jj;
        float bx = __shfl_sync(0xffffffffu, awx, srcl);
        float by = __shfl_sync(0xffffffffu, awy, srcl);
        ox = fmaf(bx, WEs[(2*jj)*64 + 2*lane],       ox);
        oy = fmaf(bx, WEs[(2*jj)*64 + 2*lane + 1],   oy);
        ox = fmaf(by, WEs[(2*jj+1)*64 + 2*lane],     ox);
        oy = fmaf(by, WEs[(2*jj+1)*64 + 2*lane + 1], oy);
    }
    float inv = 1.f / (dsum + 1e-16f);
    float2 sv = *(const float2*)(g_S + (size_t)wid*64 + 2*lane);
    float o0 = fmaxf(fmaf(ox, inv, sv.x), 0.f);
    float o1 = fmaxf(fmaf(oy, inv, sv.y), 0.f);
    float2* hp = (float2*)(g_h + (size_t)wid*64 + 2*lane);
    float2 hv = *hp;
    hv.x += o0; hv.y += o1;
    *hp = hv;
}

// ---------------- pool ----------------
__global__ void pool_kernel(const int* __restrict__ batch) {
    int c = threadIdx.x & 63;
    int sub = threadIdx.x >> 6;
    int start = blockIdx.x * 1024 + sub * 256;
    if (start >= Nn) return;
    int end = min(start + 256, Nn);
    int gprev = batch[start];
    float acc = 0.f;
    int cnt = 0;
    for (int node = start; node < end; node++) {
        int g = batch[node];
        float v = g_h[(size_t)node*64 + c];
        if (g != gprev) {
            atomicAdd(&g_pool[gprev*64 + c], acc);
            if (c == 0) atomicAdd(&g_cnt[gprev], cnt);
            acc = 0.f; cnt = 0; gprev = g;
        }
        acc += v; cnt++;
    }
    atomicAdd(&g_pool[gprev*64 + c], acc);
    if (c == 0) atomicAdd(&g_cnt[gprev], cnt);
}

// ---------------- head MLP ----------------
__global__ void final_kernel(const float* __restrict__ W1, const float* __restrict__ b1,
                             const float* __restrict__ W2, const float* __restrict__ b2,
                             float* __restrict__ out) {
    int g = blockIdx.x;
    int j = threadIdx.x;
    float invc = 1.f / fmaxf((float)g_cnt[g], 1.f);
    float acc = b1[j];
    #pragma unroll
    for (int k = 0; k < 64; k++)
        acc = fmaf(g_pool[g*64 + k] * invc, W1[k*32 + j], acc);
    acc = fmaxf(acc, 0.f);
    float t = acc * W2[j];
    #pragma unroll
    for (int o = 16; o > 0; o >>= 1) t += __shfl_xor_sync(0xffffffffu, t, o);
    if (j == 0) out[g] = t + b2[0];
}

// ---------------- launch ----------------
extern "C" void kernel_launch(void* const* d_in, const int* in_sizes, int n_in,
                              void* d_out, int out_size) {
    const float* x     = (const float*)d_in[0];
    const int*   ei    = (const int*)  d_in[1];
    const float* eattr = (const float*)d_in[2];
    const int*   batch = (const int*)  d_in[3];
    const float* Wn = (const float*)d_in[4];  const float* bn = (const float*)d_in[5];
    const float* Wq = (const float*)d_in[6];  const float* bq = (const float*)d_in[7];
    const float* Wk = (const float*)d_in[8];  const float* bk = (const float*)d_in[9];
    const float* Wv = (const float*)d_in[10]; const float* bv = (const float*)d_in[11];
    const float* We = (const float*)d_in[12];
    const float* Ws = (const float*)d_in[13]; const float* bs = (const float*)d_in[14];
    const float* W1 = (const float*)d_in[15]; const float* b1 = (const float*)d_in[16];
    const float* W2 = (const float*)d_in[17]; const float* b2 = (const float*)d_in[18];
    float* out = (float*)d_out;

    const int* src = ei;
    const int* dst = ei + Ee;

    int nblk = (Nn + 127) / 128;   // 391
    // order: capture slot #3 lands on merged gemm2 (layer 0)
    node_in_kernel<<<nblk, 256>>>(x, Wn, bn);                         // 0
    zero_kernel<<<64, 256>>>();                                       // 1
    hist_kernel<<<(Ee + 255)/256, 256>>>(dst);                        // 2
    gemm2_kernel<<<2*nblk, 256>>>(Wq, bq, Wk, bk, Wv, bv, Ws, bs, nblk); // 3
    scanA_kernel<<<NB, 1024>>>();                                     // 4
    scanBC_kernel<<<NB, 1024>>>();                                    // 5
    scatter_kernel<<<(Ee + 255)/256, 256>>>(src, dst);                // 6
    gatherE_kernel<<<(Ee*2 + 255)/256, 256>>>(eattr);                 // 7
    attn_kernel<<<(Nn*32 + 255)/256, 256>>>(We);                      // 8

    for (int l = 1; l < 3; l++) {
        const float* Wql = Wq + (size_t)l*64*64; const float* bql = bq + (size_t)l*64;
        const float* Wkl = Wk + (size_t)l*64*64; const float* bkl = bk + (size_t)l*64;
        const float* Wvl = Wv + (size_t)l*64*64; const float* bvl = bv + (size_t)l*64;
        const float* Wsl = Ws + (size_t)l*64*64; const float* bsl = bs + (size_t)l*64;
        const float* Wel = We + (size_t)l*16*64;
        gemm2_kernel<<<2*nblk, 256>>>(Wql, bql, Wkl, bkl, Wvl, bvl, Wsl, bsl, nblk);
        attn_kernel<<<(Nn*32 + 255)/256, 256>>>(Wel);
    }

    pool_kernel<<<(Nn + 1023)/1024, 256>>>(batch);
    final_kernel<<<Gg, 32>>>(W1, b1, W2, b2, out);
}